// round 1
// baseline (speedup 1.0000x reference)
#include <cuda_runtime.h>
#include <cuda_bf16.h>
#include <math.h>

// Problem constants
#define BB   32
#define TF   2048
#define TP   256
#define FD   768
#define PD   512
#define AD   512

// Scratch: q_frame [B,TF,AD] and k_phn [B,TP,AD]
__device__ float g_q[(size_t)BB * TF * AD];   // 134 MB
__device__ float g_k[(size_t)BB * TP * AD];   //  16 MB

// ---------------------------------------------------------------------------
// Generic projection GEMM: C[M,N] = A[M,K] @ W[K,N] + bias[N]
// 64x64 tile, BK=16, 256 threads, 4x4 micro-tile per thread.
// M % 64 == 0, N % 64 == 0, K % 16 == 0 (holds for our shapes).
// ---------------------------------------------------------------------------
__global__ __launch_bounds__(256)
void proj_gemm(const float* __restrict__ A, const float* __restrict__ W,
               const float* __restrict__ bias, float* __restrict__ C,
               int M, int K, int N) {
    __shared__ float a_s[16 * 68];  // [kk][m], padded
    __shared__ float b_s[16 * 64];  // [kk][n]

    const int m0 = blockIdx.y * 64;
    const int n0 = blockIdx.x * 64;
    const int t  = threadIdx.x;
    const int ty = t >> 4;   // 0..15 -> rows ty*4..+3
    const int tx = t & 15;   // 0..15 -> cols tx*4..+3

    const int lrow = t >> 2, lkq = t & 3;     // A-tile loader
    const int lkk  = t >> 4, lcq = t & 15;    // W-tile loader

    float acc[4][4];
#pragma unroll
    for (int i = 0; i < 4; i++)
#pragma unroll
        for (int j = 0; j < 4; j++) acc[i][j] = 0.0f;

    for (int k0 = 0; k0 < K; k0 += 16) {
        float4 av = *(const float4*)&A[(size_t)(m0 + lrow) * K + k0 + lkq * 4];
        a_s[(lkq * 4 + 0) * 68 + lrow] = av.x;
        a_s[(lkq * 4 + 1) * 68 + lrow] = av.y;
        a_s[(lkq * 4 + 2) * 68 + lrow] = av.z;
        a_s[(lkq * 4 + 3) * 68 + lrow] = av.w;
        *(float4*)&b_s[lkk * 64 + lcq * 4] =
            *(const float4*)&W[(size_t)(k0 + lkk) * N + n0 + lcq * 4];
        __syncthreads();
#pragma unroll
        for (int kk = 0; kk < 16; kk++) {
            float a4[4], b4[4];
            *(float4*)a4 = *(const float4*)&a_s[kk * 68 + ty * 4];
            *(float4*)b4 = *(const float4*)&b_s[kk * 64 + tx * 4];
#pragma unroll
            for (int i = 0; i < 4; i++)
#pragma unroll
                for (int j = 0; j < 4; j++)
                    acc[i][j] = fmaf(a4[i], b4[j], acc[i][j]);
        }
        __syncthreads();
    }

    float4 bv = *(const float4*)&bias[n0 + tx * 4];
#pragma unroll
    for (int i = 0; i < 4; i++) {
        float4 o;
        o.x = acc[i][0] + bv.x;
        o.y = acc[i][1] + bv.y;
        o.z = acc[i][2] + bv.z;
        o.w = acc[i][3] + bv.w;
        *(float4*)&C[(size_t)(m0 + ty * 4 + i) * N + n0 + tx * 4] = o;
    }
}

// ---------------------------------------------------------------------------
// Fused attention kernel, one block per (batch, 32-row frame tile).
// 256 threads = 8 warps; warp w owns rows w*4..w*4+3 in every phase.
// Phase 1: energy[32,256] = q_tile @ k_b^T           (micro 4x8)
//          + mask, store energy (output), warp softmax -> P in smem
// Phase 3: att[32,512] = P @ k_b                      (micro 4x16, regs)
// Phase 4: per-warp LayerNorm over concat(att, q) = 1024 from registers
// ---------------------------------------------------------------------------
// smem (floats): E_s[32][260] | kbuf[16*512] | q_s[16][36] | mask_s[256]
#define SM_E    0
#define SM_KB   (32 * 260)
#define SM_QS   (SM_KB + 16 * 512)
#define SM_MASK (SM_QS + 16 * 36)
#define SM_FLOATS (SM_MASK + 256)
#define SM_BYTES  (SM_FLOATS * 4)

__global__ __launch_bounds__(256, 2)
void fused_attn(const int* __restrict__ amask,
                const float* __restrict__ gamma,
                const float* __restrict__ beta,
                float* __restrict__ att_out,
                float* __restrict__ energy_out) {
    extern __shared__ float sm[];
    float* E_s    = sm + SM_E;     // [32][260]  energy -> P
    float* kbuf   = sm + SM_KB;    // [16][256] in phase1, [16][512] in phase3
    float* q_s    = sm + SM_QS;    // [16][36]
    float* mask_s = sm + SM_MASK;  // [256]

    const int b  = blockIdx.y;
    const int r0 = blockIdx.x * 32;
    const int t  = threadIdx.x;
    const int ty = t >> 5;   // warp id, rows ty*4..+3
    const int tx = t & 31;

    mask_s[t] = (1.0f - (float)amask[b * TP + t]) * (-1000.0f);

    const float* qbase = g_q + ((size_t)b * TF + r0) * AD;
    const float* kbase = g_k + (size_t)b * TP * AD;

    // ---------------- Phase 1: energy GEMM (32 x 256, K=512) ----------------
    float acc[4][8];
#pragma unroll
    for (int i = 0; i < 4; i++)
#pragma unroll
        for (int j = 0; j < 8; j++) acc[i][j] = 0.0f;

    for (int k0 = 0; k0 < AD; k0 += 16) {
        if (t < 128) {  // stage q chunk [32 rows][16 k] as q_s[kk][row]
            int row = t >> 2, kq = t & 3;
            float4 v = *(const float4*)&qbase[(size_t)row * AD + k0 + kq * 4];
            q_s[(kq * 4 + 0) * 36 + row] = v.x;
            q_s[(kq * 4 + 1) * 36 + row] = v.y;
            q_s[(kq * 4 + 2) * 36 + row] = v.z;
            q_s[(kq * 4 + 3) * 36 + row] = v.w;
        }
        {   // stage k chunk: p = t, 16 contiguous k values -> kbuf[kk][p]
            const float4* src = (const float4*)&kbase[(size_t)t * AD + k0];
            float4 v0 = src[0], v1 = src[1], v2 = src[2], v3 = src[3];
            kbuf[ 0 * 256 + t] = v0.x; kbuf[ 1 * 256 + t] = v0.y;
            kbuf[ 2 * 256 + t] = v0.z; kbuf[ 3 * 256 + t] = v0.w;
            kbuf[ 4 * 256 + t] = v1.x; kbuf[ 5 * 256 + t] = v1.y;
            kbuf[ 6 * 256 + t] = v1.z; kbuf[ 7 * 256 + t] = v1.w;
            kbuf[ 8 * 256 + t] = v2.x; kbuf[ 9 * 256 + t] = v2.y;
            kbuf[10 * 256 + t] = v2.z; kbuf[11 * 256 + t] = v2.w;
            kbuf[12 * 256 + t] = v3.x; kbuf[13 * 256 + t] = v3.y;
            kbuf[14 * 256 + t] = v3.z; kbuf[15 * 256 + t] = v3.w;
        }
        __syncthreads();
#pragma unroll
        for (int kk = 0; kk < 16; kk++) {
            float a4[4], bb[8];
            *(float4*)a4      = *(const float4*)&q_s[kk * 36 + ty * 4];
            *(float4*)&bb[0]  = *(const float4*)&kbuf[kk * 256 + tx * 8];
            *(float4*)&bb[4]  = *(const float4*)&kbuf[kk * 256 + tx * 8 + 4];
#pragma unroll
            for (int i = 0; i < 4; i++)
#pragma unroll
                for (int j = 0; j < 8; j++)
                    acc[i][j] = fmaf(a4[i], bb[j], acc[i][j]);
        }
        __syncthreads();
    }

    // ------- mask add, energy output, warp softmax, P -> E_s -------
#pragma unroll
    for (int i = 0; i < 4; i++) {
        const int r = ty * 4 + i;
        float e[8];
#pragma unroll
        for (int j = 0; j < 8; j++) e[j] = acc[i][j] + mask_s[tx * 8 + j];

        float* erow = energy_out + ((size_t)b * TF + r0 + r) * TP + tx * 8;
        *(float4*)(erow)     = make_float4(e[0], e[1], e[2], e[3]);
        *(float4*)(erow + 4) = make_float4(e[4], e[5], e[6], e[7]);

        float mx = e[0];
#pragma unroll
        for (int j = 1; j < 8; j++) mx = fmaxf(mx, e[j]);
#pragma unroll
        for (int o = 16; o > 0; o >>= 1)
            mx = fmaxf(mx, __shfl_xor_sync(0xffffffffu, mx, o));
        float s = 0.0f;
#pragma unroll
        for (int j = 0; j < 8; j++) { e[j] = expf(e[j] - mx); s += e[j]; }
#pragma unroll
        for (int o = 16; o > 0; o >>= 1)
            s += __shfl_xor_sync(0xffffffffu, s, o);
        const float inv = 1.0f / s;
        float* prow = &E_s[r * 260 + tx * 8];
        *(float4*)(prow)     = make_float4(e[0]*inv, e[1]*inv, e[2]*inv, e[3]*inv);
        *(float4*)(prow + 4) = make_float4(e[4]*inv, e[5]*inv, e[6]*inv, e[7]*inv);
    }
    __syncthreads();

    // ---------------- Phase 3: att GEMM (32 x 512, K=256) ----------------
    float vacc[4][16];
#pragma unroll
    for (int i = 0; i < 4; i++)
#pragma unroll
        for (int j = 0; j < 16; j++) vacc[i][j] = 0.0f;

    for (int p0 = 0; p0 < TP; p0 += 16) {
        // stage k chunk [16 p][512 cols]
#pragma unroll
        for (int rep = 0; rep < 8; rep++) {
            int idx = rep * 1024 + t * 4;
            int pr = idx >> 9, c = idx & 511;
            *(float4*)&kbuf[idx] =
                *(const float4*)&kbase[(size_t)(p0 + pr) * AD + c];
        }
        __syncthreads();
#pragma unroll
        for (int pp = 0; pp < 16; pp++) {
            float a4[4];
            a4[0] = E_s[(ty * 4 + 0) * 260 + p0 + pp];
            a4[1] = E_s[(ty * 4 + 1) * 260 + p0 + pp];
            a4[2] = E_s[(ty * 4 + 2) * 260 + p0 + pp];
            a4[3] = E_s[(ty * 4 + 3) * 260 + p0 + pp];
            float bb[16];
            const float* brow = &kbuf[pp * 512 + tx * 16];
            *(float4*)&bb[0]  = *(const float4*)(brow);
            *(float4*)&bb[4]  = *(const float4*)(brow + 4);
            *(float4*)&bb[8]  = *(const float4*)(brow + 8);
            *(float4*)&bb[12] = *(const float4*)(brow + 12);
#pragma unroll
            for (int i = 0; i < 4; i++)
#pragma unroll
                for (int j = 0; j < 16; j++)
                    vacc[i][j] = fmaf(a4[i], bb[j], vacc[i][j]);
        }
        __syncthreads();
    }

    // ---------------- Phase 4: LayerNorm over concat(att, q) ----------------
#pragma unroll
    for (int i = 0; i < 4; i++) {
        const int r = ty * 4 + i;
        float qv[16];
        const float* qrow = qbase + (size_t)r * AD + tx * 16;
        *(float4*)&qv[0]  = *(const float4*)(qrow);
        *(float4*)&qv[4]  = *(const float4*)(qrow + 4);
        *(float4*)&qv[8]  = *(const float4*)(qrow + 8);
        *(float4*)&qv[12] = *(const float4*)(qrow + 12);

        float s = 0.0f, ss = 0.0f;
#pragma unroll
        for (int j = 0; j < 16; j++) {
            float v = vacc[i][j], u = qv[j];
            s += v + u;
            ss = fmaf(v, v, ss);
            ss = fmaf(u, u, ss);
        }
#pragma unroll
        for (int o = 16; o > 0; o >>= 1) {
            s  += __shfl_xor_sync(0xffffffffu, s, o);
            ss += __shfl_xor_sync(0xffffffffu, ss, o);
        }
        const float mu  = s * (1.0f / 1024.0f);
        const float var = ss * (1.0f / 1024.0f) - mu * mu;
        const float rs  = rsqrtf(var + 1e-5f);

        float* orow = att_out + ((size_t)b * TF + r0 + r) * (2 * AD);
#pragma unroll
        for (int jj = 0; jj < 16; jj += 4) {
            int c = tx * 16 + jj;
            float4 g  = *(const float4*)&gamma[c];
            float4 be = *(const float4*)&beta[c];
            float4 o;
            o.x = (vacc[i][jj + 0] - mu) * rs * g.x + be.x;
            o.y = (vacc[i][jj + 1] - mu) * rs * g.y + be.y;
            o.z = (vacc[i][jj + 2] - mu) * rs * g.z + be.z;
            o.w = (vacc[i][jj + 3] - mu) * rs * g.w + be.w;
            *(float4*)&orow[c] = o;

            int c2 = AD + c;
            float4 g2  = *(const float4*)&gamma[c2];
            float4 be2 = *(const float4*)&beta[c2];
            float4 o2;
            o2.x = (qv[jj + 0] - mu) * rs * g2.x + be2.x;
            o2.y = (qv[jj + 1] - mu) * rs * g2.y + be2.y;
            o2.z = (qv[jj + 2] - mu) * rs * g2.z + be2.z;
            o2.w = (qv[jj + 3] - mu) * rs * g2.w + be2.w;
            *(float4*)&orow[c2] = o2;
        }
    }
}

// ---------------------------------------------------------------------------
extern "C" void kernel_launch(void* const* d_in, const int* in_sizes, int n_in,
                              void* d_out, int out_size) {
    const float* frame = (const float*)d_in[0];  // [B,TF,768]
    const float* phn   = (const float*)d_in[1];  // [B,TP,512]
    const int*   amask = (const int*)  d_in[2];  // [B,TP]
    const float* Wq    = (const float*)d_in[3];  // [768,512]
    const float* bq    = (const float*)d_in[4];  // [512]
    const float* Wk    = (const float*)d_in[5];  // [512,512]
    const float* bk    = (const float*)d_in[6];  // [512]
    const float* gamma = (const float*)d_in[7];  // [1024]
    const float* beta  = (const float*)d_in[8];  // [1024]

    float* out        = (float*)d_out;
    float* att_out    = out;                                            // [B,TF,1024]
    float* energy_out = out + ((size_t)out_size - (size_t)BB * TF * TP);// [B,TF,256]

    float *gq_ptr = nullptr, *gk_ptr = nullptr;
    cudaGetSymbolAddress((void**)&gq_ptr, g_q);
    cudaGetSymbolAddress((void**)&gk_ptr, g_k);

    // k_phn = phn @ Wk + bk   (M=8192, K=512, N=512)
    proj_gemm<<<dim3(AD / 64, (BB * TP) / 64), 256>>>(phn, Wk, bk, gk_ptr,
                                                      BB * TP, PD, AD);
    // q_frame = frame @ Wq + bq   (M=65536, K=768, N=512)
    proj_gemm<<<dim3(AD / 64, (BB * TF) / 64), 256>>>(frame, Wq, bq, gq_ptr,
                                                      BB * TF, FD, AD);

    cudaFuncSetAttribute(fused_attn, cudaFuncAttributeMaxDynamicSharedMemorySize,
                         SM_BYTES);
    fused_attn<<<dim3(TF / 32, BB), 256, SM_BYTES>>>(amask, gamma, beta,
                                                     att_out, energy_out);
}

// round 2
// speedup vs baseline: 1.0003x; 1.0003x over previous
#include <cuda_runtime.h>
#include <cuda_bf16.h>
#include <math.h>

// Problem constants
#define BB   32
#define TF   2048
#define TP   256
#define FD   768
#define PD   512
#define AD   512

// Scratch: q_frame [B,TF,AD] and k_phn [B,TP,AD]
__device__ float g_q[(size_t)BB * TF * AD];   // 134 MB
__device__ float g_k[(size_t)BB * TP * AD];   //  16 MB

// ---------------------------------------------------------------------------
// Generic projection GEMM: C[M,N] = A[M,K] @ W[K,N] + bias[N]
// 64x64 tile, BK=16, 256 threads, 4x4 micro-tile per thread.
// M % 64 == 0, N % 64 == 0, K % 16 == 0 (holds for our shapes).
// ---------------------------------------------------------------------------
__global__ __launch_bounds__(256)
void proj_gemm(const float* __restrict__ A, const float* __restrict__ W,
               const float* __restrict__ bias, float* __restrict__ C,
               int M, int K, int N) {
    __shared__ float a_s[16 * 68];  // [kk][m], padded
    __shared__ float b_s[16 * 64];  // [kk][n]

    const int m0 = blockIdx.y * 64;
    const int n0 = blockIdx.x * 64;
    const int t  = threadIdx.x;
    const int ty = t >> 4;   // 0..15 -> rows ty*4..+3
    const int tx = t & 15;   // 0..15 -> cols tx*4..+3

    const int lrow = t >> 2, lkq = t & 3;     // A-tile loader
    const int lkk  = t >> 4, lcq = t & 15;    // W-tile loader

    float acc[4][4];
#pragma unroll
    for (int i = 0; i < 4; i++)
#pragma unroll
        for (int j = 0; j < 4; j++) acc[i][j] = 0.0f;

    for (int k0 = 0; k0 < K; k0 += 16) {
        float4 av = *(const float4*)&A[(size_t)(m0 + lrow) * K + k0 + lkq * 4];
        a_s[(lkq * 4 + 0) * 68 + lrow] = av.x;
        a_s[(lkq * 4 + 1) * 68 + lrow] = av.y;
        a_s[(lkq * 4 + 2) * 68 + lrow] = av.z;
        a_s[(lkq * 4 + 3) * 68 + lrow] = av.w;
        *(float4*)&b_s[lkk * 64 + lcq * 4] =
            *(const float4*)&W[(size_t)(k0 + lkk) * N + n0 + lcq * 4];
        __syncthreads();
#pragma unroll
        for (int kk = 0; kk < 16; kk++) {
            float a4[4], b4[4];
            *(float4*)a4 = *(const float4*)&a_s[kk * 68 + ty * 4];
            *(float4*)b4 = *(const float4*)&b_s[kk * 64 + tx * 4];
#pragma unroll
            for (int i = 0; i < 4; i++)
#pragma unroll
                for (int j = 0; j < 4; j++)
                    acc[i][j] = fmaf(a4[i], b4[j], acc[i][j]);
        }
        __syncthreads();
    }

    float4 bv = *(const float4*)&bias[n0 + tx * 4];
#pragma unroll
    for (int i = 0; i < 4; i++) {
        float4 o;
        o.x = acc[i][0] + bv.x;
        o.y = acc[i][1] + bv.y;
        o.z = acc[i][2] + bv.z;
        o.w = acc[i][3] + bv.w;
        *(float4*)&C[(size_t)(m0 + ty * 4 + i) * N + n0 + tx * 4] = o;
    }
}

// ---------------------------------------------------------------------------
// Fused attention kernel, one block per (batch, 32-row frame tile).
// 256 threads = 8 warps; warp w owns rows w*4..w*4+3 in every phase.
// Phase 1: energy[32,256] = q_tile @ k_b^T           (micro 4x8)
//          + mask, store energy (output), warp softmax -> P in smem
// Phase 3: att[32,512] = P @ k_b                      (micro 4x16, regs)
// Phase 4: per-warp LayerNorm over concat(att, q) = 1024 from registers
// ---------------------------------------------------------------------------
// smem (floats): E_s[32][260] | kbuf[16*512] | q_s[16][36] | mask_s[256]
#define SM_E    0
#define SM_KB   (32 * 260)
#define SM_QS   (SM_KB + 16 * 512)
#define SM_MASK (SM_QS + 16 * 36)
#define SM_FLOATS (SM_MASK + 256)
#define SM_BYTES  (SM_FLOATS * 4)

__global__ __launch_bounds__(256, 2)
void fused_attn(const int* __restrict__ amask,
                const float* __restrict__ gamma,
                const float* __restrict__ beta,
                float* __restrict__ att_out,
                float* __restrict__ energy_out) {
    extern __shared__ float sm[];
    float* E_s    = sm + SM_E;     // [32][260]  energy -> P
    float* kbuf   = sm + SM_KB;    // [16][256] in phase1, [16][512] in phase3
    float* q_s    = sm + SM_QS;    // [16][36]
    float* mask_s = sm + SM_MASK;  // [256]

    const int b  = blockIdx.y;
    const int r0 = blockIdx.x * 32;
    const int t  = threadIdx.x;
    const int ty = t >> 5;   // warp id, rows ty*4..+3
    const int tx = t & 31;

    mask_s[t] = (1.0f - (float)amask[b * TP + t]) * (-1000.0f);

    const float* qbase = g_q + ((size_t)b * TF + r0) * AD;
    const float* kbase = g_k + (size_t)b * TP * AD;

    // ---------------- Phase 1: energy GEMM (32 x 256, K=512) ----------------
    float acc[4][8];
#pragma unroll
    for (int i = 0; i < 4; i++)
#pragma unroll
        for (int j = 0; j < 8; j++) acc[i][j] = 0.0f;

    for (int k0 = 0; k0 < AD; k0 += 16) {
        if (t < 128) {  // stage q chunk [32 rows][16 k] as q_s[kk][row]
            int row = t >> 2, kq = t & 3;
            float4 v = *(const float4*)&qbase[(size_t)row * AD + k0 + kq * 4];
            q_s[(kq * 4 + 0) * 36 + row] = v.x;
            q_s[(kq * 4 + 1) * 36 + row] = v.y;
            q_s[(kq * 4 + 2) * 36 + row] = v.z;
            q_s[(kq * 4 + 3) * 36 + row] = v.w;
        }
        {   // stage k chunk: p = t, 16 contiguous k values -> kbuf[kk][p]
            const float4* src = (const float4*)&kbase[(size_t)t * AD + k0];
            float4 v0 = src[0], v1 = src[1], v2 = src[2], v3 = src[3];
            kbuf[ 0 * 256 + t] = v0.x; kbuf[ 1 * 256 + t] = v0.y;
            kbuf[ 2 * 256 + t] = v0.z; kbuf[ 3 * 256 + t] = v0.w;
            kbuf[ 4 * 256 + t] = v1.x; kbuf[ 5 * 256 + t] = v1.y;
            kbuf[ 6 * 256 + t] = v1.z; kbuf[ 7 * 256 + t] = v1.w;
            kbuf[ 8 * 256 + t] = v2.x; kbuf[ 9 * 256 + t] = v2.y;
            kbuf[10 * 256 + t] = v2.z; kbuf[11 * 256 + t] = v2.w;
            kbuf[12 * 256 + t] = v3.x; kbuf[13 * 256 + t] = v3.y;
            kbuf[14 * 256 + t] = v3.z; kbuf[15 * 256 + t] = v3.w;
        }
        __syncthreads();
#pragma unroll
        for (int kk = 0; kk < 16; kk++) {
            float a4[4], bb[8];
            *(float4*)a4      = *(const float4*)&q_s[kk * 36 + ty * 4];
            *(float4*)&bb[0]  = *(const float4*)&kbuf[kk * 256 + tx * 8];
            *(float4*)&bb[4]  = *(const float4*)&kbuf[kk * 256 + tx * 8 + 4];
#pragma unroll
            for (int i = 0; i < 4; i++)
#pragma unroll
                for (int j = 0; j < 8; j++)
                    acc[i][j] = fmaf(a4[i], bb[j], acc[i][j]);
        }
        __syncthreads();
    }

    // ------- mask add, energy output, warp softmax, P -> E_s -------
#pragma unroll
    for (int i = 0; i < 4; i++) {
        const int r = ty * 4 + i;
        float e[8];
#pragma unroll
        for (int j = 0; j < 8; j++) e[j] = acc[i][j] + mask_s[tx * 8 + j];

        float* erow = energy_out + ((size_t)b * TF + r0 + r) * TP + tx * 8;
        *(float4*)(erow)     = make_float4(e[0], e[1], e[2], e[3]);
        *(float4*)(erow + 4) = make_float4(e[4], e[5], e[6], e[7]);

        float mx = e[0];
#pragma unroll
        for (int j = 1; j < 8; j++) mx = fmaxf(mx, e[j]);
#pragma unroll
        for (int o = 16; o > 0; o >>= 1)
            mx = fmaxf(mx, __shfl_xor_sync(0xffffffffu, mx, o));
        float s = 0.0f;
#pragma unroll
        for (int j = 0; j < 8; j++) { e[j] = expf(e[j] - mx); s += e[j]; }
#pragma unroll
        for (int o = 16; o > 0; o >>= 1)
            s += __shfl_xor_sync(0xffffffffu, s, o);
        const float inv = 1.0f / s;
        float* prow = &E_s[r * 260 + tx * 8];
        *(float4*)(prow)     = make_float4(e[0]*inv, e[1]*inv, e[2]*inv, e[3]*inv);
        *(float4*)(prow + 4) = make_float4(e[4]*inv, e[5]*inv, e[6]*inv, e[7]*inv);
    }
    __syncthreads();

    // ---------------- Phase 3: att GEMM (32 x 512, K=256) ----------------
    float vacc[4][16];
#pragma unroll
    for (int i = 0; i < 4; i++)
#pragma unroll
        for (int j = 0; j < 16; j++) vacc[i][j] = 0.0f;

    for (int p0 = 0; p0 < TP; p0 += 16) {
        // stage k chunk [16 p][512 cols]
#pragma unroll
        for (int rep = 0; rep < 8; rep++) {
            int idx = rep * 1024 + t * 4;
            int pr = idx >> 9, c = idx & 511;
            *(float4*)&kbuf[idx] =
                *(const float4*)&kbase[(size_t)(p0 + pr) * AD + c];
        }
        __syncthreads();
#pragma unroll
        for (int pp = 0; pp < 16; pp++) {
            float a4[4];
            a4[0] = E_s[(ty * 4 + 0) * 260 + p0 + pp];
            a4[1] = E_s[(ty * 4 + 1) * 260 + p0 + pp];
            a4[2] = E_s[(ty * 4 + 2) * 260 + p0 + pp];
            a4[3] = E_s[(ty * 4 + 3) * 260 + p0 + pp];
            float bb[16];
            const float* brow = &kbuf[pp * 512 + tx * 16];
            *(float4*)&bb[0]  = *(const float4*)(brow);
            *(float4*)&bb[4]  = *(const float4*)(brow + 4);
            *(float4*)&bb[8]  = *(const float4*)(brow + 8);
            *(float4*)&bb[12] = *(const float4*)(brow + 12);
#pragma unroll
            for (int i = 0; i < 4; i++)
#pragma unroll
                for (int j = 0; j < 16; j++)
                    vacc[i][j] = fmaf(a4[i], bb[j], vacc[i][j]);
        }
        __syncthreads();
    }

    // ---------------- Phase 4: LayerNorm over concat(att, q) ----------------
#pragma unroll
    for (int i = 0; i < 4; i++) {
        const int r = ty * 4 + i;
        float qv[16];
        const float* qrow = qbase + (size_t)r * AD + tx * 16;
        *(float4*)&qv[0]  = *(const float4*)(qrow);
        *(float4*)&qv[4]  = *(const float4*)(qrow + 4);
        *(float4*)&qv[8]  = *(const float4*)(qrow + 8);
        *(float4*)&qv[12] = *(const float4*)(qrow + 12);

        float s = 0.0f, ss = 0.0f;
#pragma unroll
        for (int j = 0; j < 16; j++) {
            float v = vacc[i][j], u = qv[j];
            s += v + u;
            ss = fmaf(v, v, ss);
            ss = fmaf(u, u, ss);
        }
#pragma unroll
        for (int o = 16; o > 0; o >>= 1) {
            s  += __shfl_xor_sync(0xffffffffu, s, o);
            ss += __shfl_xor_sync(0xffffffffu, ss, o);
        }
        const float mu  = s * (1.0f / 1024.0f);
        const float var = ss * (1.0f / 1024.0f) - mu * mu;
        const float rs  = rsqrtf(var + 1e-5f);

        float* orow = att_out + ((size_t)b * TF + r0 + r) * (2 * AD);
#pragma unroll
        for (int jj = 0; jj < 16; jj += 4) {
            int c = tx * 16 + jj;
            float4 g  = *(const float4*)&gamma[c];
            float4 be = *(const float4*)&beta[c];
            float4 o;
            o.x = (vacc[i][jj + 0] - mu) * rs * g.x + be.x;
            o.y = (vacc[i][jj + 1] - mu) * rs * g.y + be.y;
            o.z = (vacc[i][jj + 2] - mu) * rs * g.z + be.z;
            o.w = (vacc[i][jj + 3] - mu) * rs * g.w + be.w;
            *(float4*)&orow[c] = o;

            int c2 = AD + c;
            float4 g2  = *(const float4*)&gamma[c2];
            float4 be2 = *(const float4*)&beta[c2];
            float4 o2;
            o2.x = (qv[jj + 0] - mu) * rs * g2.x + be2.x;
            o2.y = (qv[jj + 1] - mu) * rs * g2.y + be2.y;
            o2.z = (qv[jj + 2] - mu) * rs * g2.z + be2.z;
            o2.w = (qv[jj + 3] - mu) * rs * g2.w + be2.w;
            *(float4*)&orow[c2] = o2;
        }
    }
}

// ---------------------------------------------------------------------------
extern "C" void kernel_launch(void* const* d_in, const int* in_sizes, int n_in,
                              void* d_out, int out_size) {
    const float* frame = (const float*)d_in[0];  // [B,TF,768]
    const float* phn   = (const float*)d_in[1];  // [B,TP,512]
    const int*   amask = (const int*)  d_in[2];  // [B,TP]
    const float* Wq    = (const float*)d_in[3];  // [768,512]
    const float* bq    = (const float*)d_in[4];  // [512]
    const float* Wk    = (const float*)d_in[5];  // [512,512]
    const float* bk    = (const float*)d_in[6];  // [512]
    const float* gamma = (const float*)d_in[7];  // [1024]
    const float* beta  = (const float*)d_in[8];  // [1024]

    float* out        = (float*)d_out;
    float* att_out    = out;                                            // [B,TF,1024]
    float* energy_out = out + ((size_t)out_size - (size_t)BB * TF * TP);// [B,TF,256]

    float *gq_ptr = nullptr, *gk_ptr = nullptr;
    cudaGetSymbolAddress((void**)&gq_ptr, g_q);
    cudaGetSymbolAddress((void**)&gk_ptr, g_k);

    // k_phn = phn @ Wk + bk   (M=8192, K=512, N=512)
    proj_gemm<<<dim3(AD / 64, (BB * TP) / 64), 256>>>(phn, Wk, bk, gk_ptr,
                                                      BB * TP, PD, AD);
    // q_frame = frame @ Wq + bq   (M=65536, K=768, N=512)
    proj_gemm<<<dim3(AD / 64, (BB * TF) / 64), 256>>>(frame, Wq, bq, gq_ptr,
                                                      BB * TF, FD, AD);

    cudaFuncSetAttribute(fused_attn, cudaFuncAttributeMaxDynamicSharedMemorySize,
                         SM_BYTES);
    fused_attn<<<dim3(TF / 32, BB), 256, SM_BYTES>>>(amask, gamma, beta,
                                                     att_out, energy_out);
}

// round 4
// speedup vs baseline: 3.4192x; 3.4180x over previous
#include <cuda_runtime.h>
#include <cuda_bf16.h>
#include <math.h>
#include <stdint.h>

#define BB 32
#define TF 2048
#define TP 256
#define FD 768
#define PD 512
#define AD 512
typedef __nv_bfloat16 bf16;
typedef __nv_bfloat162 bf162;

// ---------------- device scratch (no allocs allowed) ----------------
__device__ float g_q[(size_t)BB * TF * AD];          // q_frame fp32
__device__ float g_att[(size_t)BB * TF * AD];        // att pre-LN fp32
__device__ bf16 g_f_hi[(size_t)BB * TF * FD], g_f_lo[(size_t)BB * TF * FD];
__device__ bf16 g_p_hi[(size_t)BB * TP * PD], g_p_lo[(size_t)BB * TP * PD];
__device__ bf16 g_wqt_hi[AD * FD], g_wqt_lo[AD * FD];   // Wq^T [AD,FD]
__device__ bf16 g_wkt_hi[AD * PD], g_wkt_lo[AD * PD];   // Wk^T [AD,PD]
__device__ bf16 g_q_hi[(size_t)BB * TF * AD], g_q_lo[(size_t)BB * TF * AD];
__device__ bf16 g_k_hi[(size_t)BB * TP * AD], g_k_lo[(size_t)BB * TP * AD];
__device__ bf16 g_kt_hi[(size_t)BB * AD * TP], g_kt_lo[(size_t)BB * AD * TP];
__device__ bf16 g_P_hi[(size_t)BB * TF * TP], g_P_lo[(size_t)BB * TF * TP];

// ---------------- helpers ----------------
__device__ __forceinline__ uint32_t s2u(const void* p) {
    uint32_t a;
    asm("{ .reg .u64 t; cvta.to.shared.u64 t, %1; cvt.u32.u64 %0, t; }"
        : "=r"(a) : "l"(p));
    return a;
}
__device__ __forceinline__ void split1(float v, bf16& h, bf16& l) {
    h = __float2bfloat16_rn(v);
    l = __float2bfloat16_rn(v - __bfloat162float(h));
}

__device__ __forceinline__ void cp16(uint32_t dst, const void* src) {
    asm volatile("cp.async.cg.shared.global [%0], [%1], 16;"
                 :: "r"(dst), "l"(src));
}
__device__ __forceinline__ void cp_commit() {
    asm volatile("cp.async.commit_group;");
}
template <int N>
__device__ __forceinline__ void cp_wait() {
    asm volatile("cp.async.wait_group %0;" :: "n"(N));
}

__device__ __forceinline__ void ldm4(uint32_t* r, uint32_t addr) {
    asm volatile("ldmatrix.sync.aligned.m8n8.x4.shared.b16 {%0,%1,%2,%3}, [%4];"
                 : "=r"(r[0]), "=r"(r[1]), "=r"(r[2]), "=r"(r[3]) : "r"(addr));
}
__device__ __forceinline__ void mma16816(float* c, const uint32_t* a,
                                         uint32_t b0, uint32_t b1) {
    asm volatile("mma.sync.aligned.m16n8k16.row.col.f32.bf16.bf16.f32 "
                 "{%0,%1,%2,%3}, {%4,%5,%6,%7}, {%8,%9}, {%0,%1,%2,%3};"
                 : "+f"(c[0]), "+f"(c[1]), "+f"(c[2]), "+f"(c[3])
                 : "r"(a[0]), "r"(a[1]), "r"(a[2]), "r"(a[3]),
                   "r"(b0), "r"(b1));
}

// async-load one [128 x 64]bf16 tile (K-major gmem) into swizzled smem
__device__ __forceinline__ void load_tile_async(const bf16* __restrict__ src,
                                                size_t row0, int ld, int k0,
                                                uint32_t dst, int t) {
#pragma unroll
    for (int it = 0; it < 4; it++) {
        int u = it * 256 + t;
        int row = u >> 3, q = u & 7;
        cp16(dst + row * 128 + ((q ^ (row & 7)) << 4),
             src + (row0 + row) * (size_t)ld + k0 + q * 8);
    }
}

// ---------------- generic split-precision HMMA GEMM ----------------
// C[128,128] per CTA = A[128,K] @ B[128,K]^T, A/B bf16 hi+lo, fp32 accum.
// MODE: 0 projQ (+bias -> g_q fp32 + g_q_hi/lo), 1 projK (+bias -> g_k_hi/lo),
//       2 energy (+mask -> outp fp32), 3 att (-> g_att fp32)
#define GEMM_SMEM (2 * 65536)
template <int MODE>
__global__ __launch_bounds__(256, 1)
void gemm_tc(const bf16* __restrict__ Ah, const bf16* __restrict__ Al, int lda,
             int sA, const bf16* __restrict__ Bh, const bf16* __restrict__ Bl,
             int ldb, int sB, int K, const void* __restrict__ aux,
             float* __restrict__ outp) {
    extern __shared__ char sm[];
    const uint32_t sbase = s2u(sm);
    const int t = threadIdx.x, lane = t & 31, wid = t >> 5;
    const int wm = wid >> 1, wn = wid & 1;  // 4 x 2 warp grid
    const int b = blockIdx.z;
    const size_t arow0 = (size_t)b * sA + (size_t)blockIdx.y * 128;
    const size_t brow0 = (size_t)b * sB + (size_t)blockIdx.x * 128;
    const int NC = K / 64;

    float acc[2][8][4];
#pragma unroll
    for (int mt = 0; mt < 2; mt++)
#pragma unroll
        for (int nt = 0; nt < 8; nt++)
#pragma unroll
            for (int j = 0; j < 4; j++) acc[mt][nt][j] = 0.0f;

    // prologue: stage 0
    {
        uint32_t s0 = sbase;
        load_tile_async(Ah, arow0, lda, 0, s0, t);
        load_tile_async(Al, arow0, lda, 0, s0 + 16384, t);
        load_tile_async(Bh, brow0, ldb, 0, s0 + 32768, t);
        load_tile_async(Bl, brow0, ldb, 0, s0 + 49152, t);
        cp_commit();
    }

    for (int c = 0; c < NC; c++) {
        if (c + 1 < NC) {
            uint32_t sn = sbase + ((c + 1) & 1) * 65536;
            const int k0 = (c + 1) * 64;
            load_tile_async(Ah, arow0, lda, k0, sn, t);
            load_tile_async(Al, arow0, lda, k0, sn + 16384, t);
            load_tile_async(Bh, brow0, ldb, k0, sn + 32768, t);
            load_tile_async(Bl, brow0, ldb, k0, sn + 49152, t);
            cp_commit();
            cp_wait<1>();
        } else {
            cp_wait<0>();
        }
        __syncthreads();

        const uint32_t sb = sbase + (c & 1) * 65536;
        const uint32_t Ahb = sb, Alb = sb + 16384;
        const uint32_t Bhb = sb + 32768, Blb = sb + 49152;
#pragma unroll
        for (int ks = 0; ks < 4; ks++) {
            uint32_t ah[2][4], al[2][4], bh[8][2], bl[8][2];
            // A frags: row = wm*32 + mt*16 + (lane&15), q = ks*2 + (lane>>4)
#pragma unroll
            for (int mt = 0; mt < 2; mt++) {
                int row = wm * 32 + mt * 16 + (lane & 15);
                int q = ks * 2 + (lane >> 4);
                uint32_t off = row * 128 + ((q ^ (row & 7)) << 4);
                ldm4(ah[mt], Ahb + off);
                ldm4(al[mt], Alb + off);
            }
            // B frags: pairs of n-tiles per ldmatrix.x4
#pragma unroll
            for (int np = 0; np < 4; np++) {
                int g = lane >> 3, w = lane & 7;
                int ntl = np * 2 + (g >> 1);
                int row = wn * 64 + ntl * 8 + w;
                int q = ks * 2 + (g & 1);
                uint32_t off = row * 128 + ((q ^ (row & 7)) << 4);
                uint32_t r4[4];
                ldm4(r4, Bhb + off);
                bh[np * 2][0] = r4[0]; bh[np * 2][1] = r4[1];
                bh[np * 2 + 1][0] = r4[2]; bh[np * 2 + 1][1] = r4[3];
                ldm4(r4, Blb + off);
                bl[np * 2][0] = r4[0]; bl[np * 2][1] = r4[1];
                bl[np * 2 + 1][0] = r4[2]; bl[np * 2 + 1][1] = r4[3];
            }
#pragma unroll
            for (int mt = 0; mt < 2; mt++)
#pragma unroll
                for (int nt = 0; nt < 8; nt++) {
                    mma16816(acc[mt][nt], ah[mt], bh[nt][0], bh[nt][1]);
                    mma16816(acc[mt][nt], ah[mt], bl[nt][0], bl[nt][1]);
                    mma16816(acc[mt][nt], al[mt], bh[nt][0], bh[nt][1]);
                }
        }
        __syncthreads();
    }

    // ---------------- epilogue ----------------
#pragma unroll
    for (int mt = 0; mt < 2; mt++)
#pragma unroll
        for (int h = 0; h < 2; h++) {
            const int rl = wm * 32 + mt * 16 + (lane >> 2) + h * 8;
#pragma unroll
            for (int nt = 0; nt < 8; nt++) {
                const int cl = wn * 64 + nt * 8 + (lane & 3) * 2;
                float v0 = acc[mt][nt][h * 2];
                float v1 = acc[mt][nt][h * 2 + 1];
                if (MODE == 0 || MODE == 1) {
                    const float* bias = (const float*)aux;
                    const size_t gr = (size_t)blockIdx.y * 128 + rl;
                    const int gc = blockIdx.x * 128 + cl;
                    v0 += bias[gc];
                    v1 += bias[gc + 1];
                    bf16 h0, l0, h1, l1;
                    split1(v0, h0, l0);
                    split1(v1, h1, l1);
                    bf162 ph; ph.x = h0; ph.y = h1;
                    bf162 pl; pl.x = l0; pl.y = l1;
                    if (MODE == 0) {
                        *(float2*)&g_q[gr * AD + gc] = make_float2(v0, v1);
                        *(bf162*)&g_q_hi[gr * AD + gc] = ph;
                        *(bf162*)&g_q_lo[gr * AD + gc] = pl;
                    } else {
                        *(bf162*)&g_k_hi[gr * AD + gc] = ph;
                        *(bf162*)&g_k_lo[gr * AD + gc] = pl;
                    }
                } else if (MODE == 2) {
                    const int* am = (const int*)aux;
                    const int mrow = blockIdx.y * 128 + rl;
                    const int gcol = blockIdx.x * 128 + cl;
                    v0 += (1.0f - (float)am[b * TP + gcol]) * (-1000.0f);
                    v1 += (1.0f - (float)am[b * TP + gcol + 1]) * (-1000.0f);
                    *(float2*)&outp[((size_t)b * TF + mrow) * TP + gcol] =
                        make_float2(v0, v1);
                } else {
                    const int mrow = blockIdx.y * 128 + rl;
                    const int gcol = blockIdx.x * 128 + cl;
                    *(float2*)&g_att[((size_t)b * TF + mrow) * AD + gcol] =
                        make_float2(v0, v1);
                }
            }
        }
}

// ---------------- pointwise kernels ----------------
__global__ void split_k(const float* __restrict__ in, bf16* __restrict__ hi,
                        bf16* __restrict__ lo, size_t n4) {
    size_t i = (size_t)blockIdx.x * blockDim.x + threadIdx.x;
    if (i >= n4) return;
    float4 v = ((const float4*)in)[i];
    bf16 h0, h1, h2, h3, l0, l1, l2, l3;
    split1(v.x, h0, l0); split1(v.y, h1, l1);
    split1(v.z, h2, l2); split1(v.w, h3, l3);
    bf162 a, b;
    a.x = h0; a.y = h1; b.x = h2; b.y = h3;
    ((bf162*)hi)[i * 2] = a; ((bf162*)hi)[i * 2 + 1] = b;
    a.x = l0; a.y = l1; b.x = l2; b.y = l3;
    ((bf162*)lo)[i * 2] = a; ((bf162*)lo)[i * 2 + 1] = b;
}

__global__ void tsplit_k(const float* __restrict__ W, bf16* __restrict__ hiT,
                         bf16* __restrict__ loT, int K, int N) {
    __shared__ float tile[32][33];
    const int n0 = blockIdx.x * 32, k0 = blockIdx.y * 32;
    for (int r = threadIdx.y; r < 32; r += 8)
        tile[r][threadIdx.x] = W[(size_t)(k0 + r) * N + n0 + threadIdx.x];
    __syncthreads();
    for (int r = threadIdx.y; r < 32; r += 8) {
        float v = tile[threadIdx.x][r];
        bf16 h, l;
        split1(v, h, l);
        hiT[(size_t)(n0 + r) * K + k0 + threadIdx.x] = h;
        loT[(size_t)(n0 + r) * K + k0 + threadIdx.x] = l;
    }
}

// transpose [B*TP, AD] bf16 -> [B, AD, TP]
__global__ void transpose_bf(const bf16* __restrict__ in, bf16* __restrict__ out) {
    __shared__ bf16 tile[32][33];
    const int r0 = blockIdx.y * 32, c0 = blockIdx.x * 32;
    for (int r = threadIdx.y; r < 32; r += 8)
        tile[r][threadIdx.x] = in[(size_t)(r0 + r) * AD + c0 + threadIdx.x];
    __syncthreads();
    const int b = r0 >> 8, p0 = r0 & 255;
    for (int r = threadIdx.y; r < 32; r += 8)
        out[((size_t)b * AD + c0 + r) * TP + p0 + threadIdx.x] = tile[threadIdx.x][r];
}

// warp-per-row softmax over energy (already masked) -> P hi/lo bf16
__global__ __launch_bounds__(256)
void softmax_k(const float* __restrict__ energy) {
    const int lane = threadIdx.x & 31, wid = threadIdx.x >> 5;
    const size_t row = (size_t)blockIdx.x * 8 + wid;
    const float* e = energy + row * TP + lane * 8;
    float v[8];
    *(float4*)&v[0] = *(const float4*)(e);
    *(float4*)&v[4] = *(const float4*)(e + 4);
    float mx = v[0];
#pragma unroll
    for (int j = 1; j < 8; j++) mx = fmaxf(mx, v[j]);
#pragma unroll
    for (int o = 16; o > 0; o >>= 1)
        mx = fmaxf(mx, __shfl_xor_sync(0xffffffffu, mx, o));
    float s = 0.0f;
#pragma unroll
    for (int j = 0; j < 8; j++) { v[j] = expf(v[j] - mx); s += v[j]; }
#pragma unroll
    for (int o = 16; o > 0; o >>= 1)
        s += __shfl_xor_sync(0xffffffffu, s, o);
    const float inv = 1.0f / s;
    bf16* ph = g_P_hi + row * TP + lane * 8;
    bf16* pl = g_P_lo + row * TP + lane * 8;
#pragma unroll
    for (int j = 0; j < 8; j += 2) {
        bf16 h0, l0, h1, l1;
        split1(v[j] * inv, h0, l0);
        split1(v[j + 1] * inv, h1, l1);
        bf162 a; a.x = h0; a.y = h1; *(bf162*)(ph + j) = a;
        bf162 c; c.x = l0; c.y = l1; *(bf162*)(pl + j) = c;
    }
}

// warp-per-row LayerNorm over concat(att[512], q[512])
__global__ __launch_bounds__(256)
void ln_k(const float* __restrict__ gamma, const float* __restrict__ beta,
          float* __restrict__ att_out) {
    const int lane = threadIdx.x & 31, wid = threadIdx.x >> 5;
    const size_t row = (size_t)blockIdx.x * 8 + wid;
    const float4* arow = (const float4*)(g_att + row * AD) + lane * 4;
    const float4* qrow = (const float4*)(g_q + row * AD) + lane * 4;
    float4 av[4], qv[4];
    float s = 0.0f, ss = 0.0f;
#pragma unroll
    for (int u = 0; u < 4; u++) {
        av[u] = arow[u];
        qv[u] = qrow[u];
        s += av[u].x + av[u].y + av[u].z + av[u].w;
        s += qv[u].x + qv[u].y + qv[u].z + qv[u].w;
        ss = fmaf(av[u].x, av[u].x, ss); ss = fmaf(av[u].y, av[u].y, ss);
        ss = fmaf(av[u].z, av[u].z, ss); ss = fmaf(av[u].w, av[u].w, ss);
        ss = fmaf(qv[u].x, qv[u].x, ss); ss = fmaf(qv[u].y, qv[u].y, ss);
        ss = fmaf(qv[u].z, qv[u].z, ss); ss = fmaf(qv[u].w, qv[u].w, ss);
    }
#pragma unroll
    for (int o = 16; o > 0; o >>= 1) {
        s  += __shfl_xor_sync(0xffffffffu, s, o);
        ss += __shfl_xor_sync(0xffffffffu, ss, o);
    }
    const float mu = s * (1.0f / 1024.0f);
    const float var = ss * (1.0f / 1024.0f) - mu * mu;
    const float rs = rsqrtf(var + 1e-5f);
    float* orow = att_out + row * 1024;
#pragma unroll
    for (int u = 0; u < 4; u++) {
        int c = lane * 16 + u * 4;
        float4 g = *(const float4*)(gamma + c);
        float4 be = *(const float4*)(beta + c);
        float4 o;
        o.x = (av[u].x - mu) * rs * g.x + be.x;
        o.y = (av[u].y - mu) * rs * g.y + be.y;
        o.z = (av[u].z - mu) * rs * g.z + be.z;
        o.w = (av[u].w - mu) * rs * g.w + be.w;
        *(float4*)(orow + c) = o;
        int c2 = AD + c;
        g = *(const float4*)(gamma + c2);
        be = *(const float4*)(beta + c2);
        o.x = (qv[u].x - mu) * rs * g.x + be.x;
        o.y = (qv[u].y - mu) * rs * g.y + be.y;
        o.z = (qv[u].z - mu) * rs * g.z + be.z;
        o.w = (qv[u].w - mu) * rs * g.w + be.w;
        *(float4*)(orow + c2) = o;
    }
}

// ---------------------------------------------------------------------------
extern "C" void kernel_launch(void* const* d_in, const int* in_sizes, int n_in,
                              void* d_out, int out_size) {
    const float* frame = (const float*)d_in[0];
    const float* phn   = (const float*)d_in[1];
    const int*   amask = (const int*)  d_in[2];
    const float* Wq    = (const float*)d_in[3];
    const float* bq    = (const float*)d_in[4];
    const float* Wk    = (const float*)d_in[5];
    const float* bk    = (const float*)d_in[6];
    const float* gamma = (const float*)d_in[7];
    const float* beta  = (const float*)d_in[8];

    float* out        = (float*)d_out;
    float* att_out    = out;
    float* energy_out = out + ((size_t)out_size - (size_t)BB * TF * TP);

    cudaFuncSetAttribute(gemm_tc<0>, cudaFuncAttributeMaxDynamicSharedMemorySize, GEMM_SMEM);
    cudaFuncSetAttribute(gemm_tc<1>, cudaFuncAttributeMaxDynamicSharedMemorySize, GEMM_SMEM);
    cudaFuncSetAttribute(gemm_tc<2>, cudaFuncAttributeMaxDynamicSharedMemorySize, GEMM_SMEM);
    cudaFuncSetAttribute(gemm_tc<3>, cudaFuncAttributeMaxDynamicSharedMemorySize, GEMM_SMEM);

    bf16 *fh, *fl, *ph_, *pl_, *wqh, *wql, *wkh, *wkl;
    bf16 *qh, *ql, *kh, *kl, *kth, *ktl, *Ph, *Pl;
    cudaGetSymbolAddress((void**)&fh, g_f_hi);
    cudaGetSymbolAddress((void**)&fl, g_f_lo);
    cudaGetSymbolAddress((void**)&ph_, g_p_hi);
    cudaGetSymbolAddress((void**)&pl_, g_p_lo);
    cudaGetSymbolAddress((void**)&wqh, g_wqt_hi);
    cudaGetSymbolAddress((void**)&wql, g_wqt_lo);
    cudaGetSymbolAddress((void**)&wkh, g_wkt_hi);
    cudaGetSymbolAddress((void**)&wkl, g_wkt_lo);
    cudaGetSymbolAddress((void**)&qh, g_q_hi);
    cudaGetSymbolAddress((void**)&ql, g_q_lo);
    cudaGetSymbolAddress((void**)&kh, g_k_hi);
    cudaGetSymbolAddress((void**)&kl, g_k_lo);
    cudaGetSymbolAddress((void**)&kth, g_kt_hi);
    cudaGetSymbolAddress((void**)&ktl, g_kt_lo);
    cudaGetSymbolAddress((void**)&Ph, g_P_hi);
    cudaGetSymbolAddress((void**)&Pl, g_P_lo);

    // 1) splits of inputs + transposed-split weights
    {
        size_t n4 = (size_t)BB * TF * FD / 4;
        split_k<<<(unsigned)(n4 / 256), 256>>>(frame, fh, fl, n4);
    }
    {
        size_t n4 = (size_t)BB * TP * PD / 4;
        split_k<<<(unsigned)(n4 / 256), 256>>>(phn, ph_, pl_, n4);
    }
    tsplit_k<<<dim3(AD / 32, FD / 32), dim3(32, 8)>>>(Wq, wqh, wql, FD, AD);
    tsplit_k<<<dim3(AD / 32, PD / 32), dim3(32, 8)>>>(Wk, wkh, wkl, PD, AD);

    // 2) K projection: [8192,512] = phn @ Wk^T(+bk)
    gemm_tc<1><<<dim3(4, 64, 1), 256, GEMM_SMEM>>>(ph_, pl_, PD, 0, wkh, wkl,
                                                   PD, 0, PD, bk, nullptr);
    // 3) K^T for the att GEMM
    transpose_bf<<<dim3(AD / 32, BB * TP / 32), dim3(32, 8)>>>(kh, kth);
    transpose_bf<<<dim3(AD / 32, BB * TP / 32), dim3(32, 8)>>>(kl, ktl);

    // 4) Q projection: [65536,512] = frame @ Wq^T(+bq)
    gemm_tc<0><<<dim3(4, 512, 1), 256, GEMM_SMEM>>>(fh, fl, FD, 0, wqh, wql,
                                                    FD, 0, FD, bq, nullptr);

    // 5) energy = q @ k^T + mask  (batched)
    gemm_tc<2><<<dim3(2, 16, BB), 256, GEMM_SMEM>>>(qh, ql, AD, TF, kh, kl,
                                                    AD, TP, AD, amask, energy_out);

    // 6) softmax rows -> P hi/lo
    softmax_k<<<BB * TF / 8, 256>>>(energy_out);

    // 7) att = P @ k  (batched, via k^T rows)
    gemm_tc<3><<<dim3(4, 16, BB), 256, GEMM_SMEM>>>(Ph, Pl, TP, TF, kth, ktl,
                                                    TP, AD, TP, nullptr, nullptr);

    // 8) LayerNorm over concat(att, q)
    ln_k<<<BB * TF / 8, 256>>>(gamma, beta, att_out);
}